// round 2
// baseline (speedup 1.0000x reference)
#include <cuda_runtime.h>

#define N_NODES 128
#define V_PTS   2048
#define XYZ     63
#define NG      9          // node groups (8 groups of 15 + 1 group of 8)

typedef unsigned long long ull;

// ---- scratch (__device__ globals: allocation-free rule) ----
__device__ float g_ei[N_NODES * 32];
__device__ float g_b1eff[N_NODES * 64];
__device__ float g_e[N_NODES * V_PTS];            // normalized blend weights (0 if masked)
__device__ float g_fpart[NG * V_PTS * 256];       // per-group partial blended features (18.9 MB)
// pre-transposed weights ([k][j] / [k][c] layouts for conflict-free staging)
__device__ float g_W1t[N_NODES * 63 * 64];
__device__ float g_W2t[N_NODES * 64 * 64];
__device__ float g_W3t[N_NODES * 64 * 64];
__device__ float g_W4t[N_NODES * 64 * 256];

// ---- output layout ----
#define OFF_C      0
#define OFF_D      6144
#define OFF_EI     8192
#define OFF_DELTA  12288
#define OFF_MEAN   12672
#define OFF_LOGVAR 13696

// ---- packed f32x2 helpers ----
__device__ __forceinline__ void fma2(ull& d, ull a, ull b) {
    asm("fma.rn.f32x2 %0, %1, %2, %0;" : "+l"(d) : "l"(a), "l"(b));
}
__device__ __forceinline__ ull dup2(float x) {
    ull r; asm("mov.b64 %0, {%1, %1};" : "=l"(r) : "r"(__float_as_uint(x)));
    return r;
}
__device__ __forceinline__ float2 unpk(ull a) {
    unsigned lo, hi;
    asm("mov.b64 {%0, %1}, %2;" : "=r"(lo), "=r"(hi) : "l"(a));
    return make_float2(__uint_as_float(lo), __uint_as_float(hi));
}

// =====================================================================
// Kernel A: per-node encoder + decoder + effective layer-1 bias
// =====================================================================
__global__ void setup_kernel(
    const float* __restrict__ poses, const float* __restrict__ t_ped,
    const float* __restrict__ w,
    const float* __restrict__ Wec1, const float* __restrict__ bec1,
    const float* __restrict__ Wec21, const float* __restrict__ bec21,
    const float* __restrict__ Wec22, const float* __restrict__ bec22,
    const float* __restrict__ Wdc1, const float* __restrict__ bdc1,
    const float* __restrict__ Wdc21, const float* __restrict__ bdc21,
    const float* __restrict__ Wdc22, const float* __restrict__ bdc22,
    const float* __restrict__ Wf1, const float* __restrict__ bf1,
    float* __restrict__ out)
{
    int n = blockIdx.x;
    int t = threadIdx.x;            // 128 threads
    __shared__ float s_in[88];
    __shared__ float s_net[64];
    __shared__ float s_mean[8];
    __shared__ float s_din[80];
    __shared__ float s_net2[64];
    __shared__ float s_ei[32];

    if (t < 72)       s_in[t] = w[n * 24 + t / 3] * poses[n * 72 + t];
    else if (t < 88)  s_in[t] = t_ped[t - 72];
    __syncthreads();

    if (t < 64) {
        float a = bec1[n * 64 + t];
        const float* Wr = &Wec1[(n * 64 + t) * 88];
        #pragma unroll 8
        for (int c = 0; c < 88; c++) a += Wr[c] * s_in[c];
        s_net[t] = fmaxf(a, 0.f);
    }
    __syncthreads();

    if (t < 8) {
        float m  = bec21[n * 8 + t];
        float lv = bec22[n * 8 + t];
        const float* Wm = &Wec21[(n * 8 + t) * 64];
        const float* Wl = &Wec22[(n * 8 + t) * 64];
        #pragma unroll 8
        for (int c = 0; c < 64; c++) { m += Wm[c] * s_net[c]; lv += Wl[c] * s_net[c]; }
        s_mean[t] = m;
        out[OFF_MEAN   + n * 8 + t] = m;
        out[OFF_LOGVAR + n * 8 + t] = lv;
    }
    __syncthreads();

    if (t < 72)       s_din[t] = s_in[t];
    else if (t < 80)  s_din[t] = s_mean[t - 72];
    __syncthreads();

    if (t < 64) {
        float a = bdc1[n * 64 + t];
        const float* Wr = &Wdc1[(n * 64 + t) * 80];
        #pragma unroll 8
        for (int c = 0; c < 80; c++) a += Wr[c] * s_din[c];
        s_net2[t] = fmaxf(a, 0.f);
    }
    __syncthreads();

    if (t < 32) {
        float a = bdc21[n * 32 + t];
        const float* Wr = &Wdc21[(n * 32 + t) * 64];
        #pragma unroll 8
        for (int c = 0; c < 64; c++) a += Wr[c] * s_net2[c];
        s_ei[t] = a;
        g_ei[n * 32 + t] = a;
        out[OFF_EI + n * 32 + t] = a;
    }
    if (t >= 32 && t < 35) {
        int j = t - 32;
        float a = bdc22[n * 3 + j];
        const float* Wr = &Wdc22[(n * 3 + j) * 64];
        #pragma unroll 8
        for (int c = 0; c < 64; c++) a += Wr[c] * s_net2[c];
        out[OFF_DELTA + n * 3 + j] = a;
    }
    __syncthreads();

    if (t < 64) {
        float a = bf1[n * 64 + t];
        const float* Wr = &Wf1[(size_t)(n * 64 + t) * 95];
        #pragma unroll 8
        for (int c = 0; c < 32; c++) a += Wr[c] * s_ei[c];
        g_b1eff[n * 64 + t] = a;
    }
}

// =====================================================================
// Kernel B: RBF blend weights, normalized
// =====================================================================
__global__ void bweight_kernel(const float* __restrict__ wpts,
                               const float* __restrict__ nodes_posed)
{
    int v = blockIdx.x * blockDim.x + threadIdx.x;
    if (v >= V_PTS) return;
    float px = wpts[v * 3 + 0], py = wpts[v * 3 + 1], pz = wpts[v * 3 + 2];
    float denom = 0.f;
    for (int n = 0; n < N_NODES; n++) {
        float dx = px - nodes_posed[n * 3 + 0];
        float dy = py - nodes_posed[n * 3 + 1];
        float dz = pz - nodes_posed[n * 3 + 2];
        float d2 = dx * dx + dy * dy + dz * dz;
        float influ = expf(-d2 * (1.0f / 0.18f)) - 0.01f;
        float e = (influ >= 0.f) ? (influ + 1e-7f) : 0.f;
        denom += fmaxf(influ, 0.f) + 1e-7f;
        g_e[n * V_PTS + v] = e;
    }
    float inv = 1.0f / denom;
    for (int n = 0; n < N_NODES; n++) g_e[n * V_PTS + v] *= inv;
}

// =====================================================================
// Kernel E: pre-transpose weights into [k][j] / [k][c] layouts
// grid = 128 (one block per node), 256 threads
// =====================================================================
__global__ void transpose_kernel(const float* __restrict__ Wf1,
                                 const float* __restrict__ Wf2,
                                 const float* __restrict__ Wf3,
                                 const float* __restrict__ Wf4)
{
    __shared__ float t[64][65];
    int n = blockIdx.x;
    int tid = threadIdx.x;

    // W1: [j][95] cols 32.. -> [k][j], k<63
    for (int idx = tid; idx < 4096; idx += 256) {
        int j = idx >> 6, k = idx & 63;
        t[j][k] = (k < 63) ? Wf1[(size_t)(n * 64 + j) * 95 + 32 + k] : 0.f;
    }
    __syncthreads();
    for (int idx = tid; idx < 63 * 64; idx += 256) {
        int k = idx >> 6, j = idx & 63;
        g_W1t[(size_t)n * 4032 + idx] = t[j][k];
    }
    __syncthreads();

    // W2
    for (int idx = tid; idx < 4096; idx += 256) {
        int j = idx >> 6, k = idx & 63;
        t[j][k] = Wf2[(size_t)n * 4096 + idx];
    }
    __syncthreads();
    for (int idx = tid; idx < 4096; idx += 256) {
        int k = idx >> 6, j = idx & 63;
        g_W2t[(size_t)n * 4096 + idx] = t[j][k];
    }
    __syncthreads();

    // W3
    for (int idx = tid; idx < 4096; idx += 256) {
        int j = idx >> 6, k = idx & 63;
        t[j][k] = Wf3[(size_t)n * 4096 + idx];
    }
    __syncthreads();
    for (int idx = tid; idx < 4096; idx += 256) {
        int k = idx >> 6, j = idx & 63;
        g_W3t[(size_t)n * 4096 + idx] = t[j][k];
    }
    __syncthreads();

    // W4: [c][k] -> [k][c], 4 chunks of 64 c
    for (int c0 = 0; c0 < 256; c0 += 64) {
        for (int idx = tid; idx < 4096; idx += 256) {
            int cc = idx >> 6, k = idx & 63;
            t[cc][k] = Wf4[(size_t)n * 16384 + (size_t)(c0 + cc) * 64 + k];
        }
        __syncthreads();
        for (int idx = tid; idx < 4096; idx += 256) {
            int k = idx >> 6, cc = idx & 63;
            g_W4t[(size_t)n * 16384 + (size_t)k * 256 + c0 + cc] = t[cc][k];
        }
        __syncthreads();
    }
}

// =====================================================================
// Kernel C: feature field (packed f32x2 FFMA)
// grid = (16 v-tiles of 128 pts) x (9 node-groups), 512 threads
// =====================================================================
#define SM_BUFA 0        // 64 x 132 activation buffer ([k][v] transposed)
#define SM_BUFB 8448
#define SM_W1   16896    // [k][j] stride 72
#define SM_W2   21504
#define SM_W3   26112
#define SM_W4   30720    // [k][c] stride 260
#define SM_B1   47360
#define SM_B2   47424
#define SM_B3   47488
#define SM_B4   47552
#define SM_E    47808
#define SM_TOT  47936    // floats -> 191744 bytes

template <int K>
__device__ __forceinline__ void gemm_layer(const float* __restrict__ in_s,
                                           const float* __restrict__ W_s,
                                           const float* __restrict__ b_s,
                                           float* __restrict__ out_s,
                                           int jq, int vq)
{
    // out[v][j] = relu(b[j] + sum_k W[k][j] * in[k][v]); 4v x 4j, packed over v
    ull acc[2][4];
    #pragma unroll
    for (int p = 0; p < 2; p++)
        #pragma unroll
        for (int j = 0; j < 4; j++) acc[p][j] = 0ull;

    int v0 = vq * 4, j0 = jq * 4;
    #pragma unroll 4
    for (int k = 0; k < K; k++) {
        ulonglong2 av = *(const ulonglong2*)&in_s[k * 132 + v0];
        float4 wj = *(const float4*)&W_s[k * 72 + j0];
        ull w0 = dup2(wj.x), w1 = dup2(wj.y), w2 = dup2(wj.z), w3 = dup2(wj.w);
        fma2(acc[0][0], av.x, w0); fma2(acc[1][0], av.y, w0);
        fma2(acc[0][1], av.x, w1); fma2(acc[1][1], av.y, w1);
        fma2(acc[0][2], av.x, w2); fma2(acc[1][2], av.y, w2);
        fma2(acc[0][3], av.x, w3); fma2(acc[1][3], av.y, w3);
    }
    #pragma unroll
    for (int dj = 0; dj < 4; dj++) {
        float bj = b_s[j0 + dj];
        float2 lo = unpk(acc[0][dj]);
        float2 hi = unpk(acc[1][dj]);
        float4 o;
        o.x = fmaxf(lo.x + bj, 0.f);
        o.y = fmaxf(lo.y + bj, 0.f);
        o.z = fmaxf(hi.x + bj, 0.f);
        o.w = fmaxf(hi.y + bj, 0.f);
        *(float4*)&out_s[(j0 + dj) * 132 + v0] = o;
    }
}

__global__ void __launch_bounds__(512, 1) field_kernel(
    const float* __restrict__ local_coords,
    const float* __restrict__ bf2, const float* __restrict__ bf3,
    const float* __restrict__ bf4)
{
    extern __shared__ float sm[];
    int tid = threadIdx.x;
    int v0 = blockIdx.x * 128;
    int g  = blockIdx.y;
    int n0   = g * 15;
    int ncnt = (g == 8) ? 8 : 15;

    float acc[8][8];
    #pragma unroll
    for (int i = 0; i < 8; i++)
        #pragma unroll
        for (int j = 0; j < 8; j++) acc[i][j] = 0.f;

    int jq  = tid & 15, vq4 = tid >> 4;   // layers 1-3 (4v x 4j)
    int cq  = tid & 31, vq8 = tid >> 5;   // layer 4 (8v x 8c)
    int vv8 = vq8 * 8;

    for (int ni = 0; ni < ncnt; ni++) {
        int n = n0 + ni;

        // ---- stage node data into smem (vectorized where possible) ----
        for (int idx = tid; idx < 128 * XYZ; idx += 512) {
            int v = idx / XYZ, k = idx - v * XYZ;
            sm[SM_BUFA + k * 132 + v] =
                local_coords[((size_t)n * V_PTS + v0 + v) * XYZ + k];
        }
        for (int f = tid; f < 63 * 16; f += 512) {          // W1: [k][j]
            int k = f >> 4, j4 = (f & 15) * 4;
            float4 w = *(const float4*)&g_W1t[(size_t)n * 4032 + k * 64 + j4];
            *(float4*)&sm[SM_W1 + k * 72 + j4] = w;
        }
        for (int f = tid; f < 1024; f += 512) {             // W2, W3
            int k = f >> 4, j4 = (f & 15) * 4;
            float4 w2 = *(const float4*)&g_W2t[(size_t)n * 4096 + k * 64 + j4];
            float4 w3 = *(const float4*)&g_W3t[(size_t)n * 4096 + k * 64 + j4];
            *(float4*)&sm[SM_W2 + k * 72 + j4] = w2;
            *(float4*)&sm[SM_W3 + k * 72 + j4] = w3;
        }
        for (int f = tid; f < 4096; f += 512) {             // W4: [k][c]
            int k = f >> 6, c4 = (f & 63) * 4;
            float4 w = *(const float4*)&g_W4t[(size_t)n * 16384 + (size_t)k * 256 + c4];
            *(float4*)&sm[SM_W4 + k * 260 + c4] = w;
        }
        if (tid < 64) {
            sm[SM_B1 + tid] = g_b1eff[n * 64 + tid];
            sm[SM_B2 + tid] = bf2[n * 64 + tid];
            sm[SM_B3 + tid] = bf3[n * 64 + tid];
        }
        if (tid < 256) sm[SM_B4 + tid] = bf4[n * 256 + tid];
        if (tid < 128) sm[SM_E + tid] = g_e[n * V_PTS + v0 + tid];
        __syncthreads();

        float ev[8];
        #pragma unroll
        for (int i = 0; i < 8; i++) ev[i] = sm[SM_E + vv8 + i];

        // ---- L1 -> L2 -> L3 ----
        gemm_layer<63>(sm + SM_BUFA, sm + SM_W1, sm + SM_B1, sm + SM_BUFB, jq, vq4);
        __syncthreads();
        gemm_layer<64>(sm + SM_BUFB, sm + SM_W2, sm + SM_B2, sm + SM_BUFA, jq, vq4);
        __syncthreads();
        gemm_layer<64>(sm + SM_BUFA, sm + SM_W3, sm + SM_B3, sm + SM_BUFB, jq, vq4);
        __syncthreads();

        // ---- L4 (256 outputs) fused with weighted blend-accumulate ----
        #pragma unroll
        for (int h = 0; h < 2; h++) {
            int c0 = h * 128 + cq * 4;
            ull t[4][4];
            #pragma unroll
            for (int p = 0; p < 4; p++)
                #pragma unroll
                for (int j = 0; j < 4; j++) t[p][j] = 0ull;

            #pragma unroll 2
            for (int k = 0; k < 64; k++) {
                ulonglong2 a01 = *(const ulonglong2*)&sm[SM_BUFB + k * 132 + vv8];
                ulonglong2 a23 = *(const ulonglong2*)&sm[SM_BUFB + k * 132 + vv8 + 4];
                float4 wc = *(const float4*)&sm[SM_W4 + k * 260 + c0];
                ull w0 = dup2(wc.x), w1 = dup2(wc.y), w2 = dup2(wc.z), w3 = dup2(wc.w);
                fma2(t[0][0], a01.x, w0); fma2(t[1][0], a01.y, w0);
                fma2(t[2][0], a23.x, w0); fma2(t[3][0], a23.y, w0);
                fma2(t[0][1], a01.x, w1); fma2(t[1][1], a01.y, w1);
                fma2(t[2][1], a23.x, w1); fma2(t[3][1], a23.y, w1);
                fma2(t[0][2], a01.x, w2); fma2(t[1][2], a01.y, w2);
                fma2(t[2][2], a23.x, w2); fma2(t[3][2], a23.y, w2);
                fma2(t[0][3], a01.x, w3); fma2(t[1][3], a01.y, w3);
                fma2(t[2][3], a23.x, w3); fma2(t[3][3], a23.y, w3);
            }
            float4 bb = *(const float4*)&sm[SM_B4 + c0];
            float bbv[4] = {bb.x, bb.y, bb.z, bb.w};
            #pragma unroll
            for (int dc = 0; dc < 4; dc++) {
                #pragma unroll
                for (int p = 0; p < 4; p++) {
                    float2 f = unpk(t[p][dc]);
                    float f0 = fmaxf(f.x + bbv[dc], 0.f);
                    float f1 = fmaxf(f.y + bbv[dc], 0.f);
                    acc[2 * p][h * 4 + dc]     += ev[2 * p] * f0;
                    acc[2 * p + 1][h * 4 + dc] += ev[2 * p + 1] * f1;
                }
            }
        }
        __syncthreads();
    }

    // ---- write this group's partial tile ----
    #pragma unroll
    for (int dv = 0; dv < 8; dv++) {
        size_t base = ((size_t)g * V_PTS + v0 + vv8 + dv) * 256;
        float4 lo = make_float4(acc[dv][0], acc[dv][1], acc[dv][2], acc[dv][3]);
        float4 hi = make_float4(acc[dv][4], acc[dv][5], acc[dv][6], acc[dv][7]);
        *(float4*)&g_fpart[base + cq * 4]       = lo;
        *(float4*)&g_fpart[base + 128 + cq * 4] = hi;
    }
}

// =====================================================================
// Kernel D: reduce partials + NeRF head
// =====================================================================
__global__ void head_kernel(const float* __restrict__ Wc1, const float* __restrict__ bc1,
                            const float* __restrict__ Wc2, const float* __restrict__ bc2,
                            const float* __restrict__ Wd1, const float* __restrict__ bd1,
                            float* __restrict__ out)
{
    int v = blockIdx.x;
    int t = threadIdx.x;   // 64 threads
    __shared__ float f_s[256];
    __shared__ float netc_s[64];

    {
        float4 s = make_float4(0.f, 0.f, 0.f, 0.f);
        #pragma unroll
        for (int g2 = 0; g2 < NG; g2++) {
            float4 p = *(const float4*)&g_fpart[((size_t)g2 * V_PTS + v) * 256 + t * 4];
            s.x += p.x; s.y += p.y; s.z += p.z; s.w += p.w;
        }
        *(float4*)&f_s[t * 4] = s;
    }
    __syncthreads();

    float a = bc1[t];
    #pragma unroll 8
    for (int c = 0; c < 256; c++) a += f_s[c] * Wc1[c * 64 + t];
    netc_s[t] = fmaxf(a, 0.f);
    __syncthreads();

    if (t < 3) {
        float r = bc2[t];
        #pragma unroll 8
        for (int j = 0; j < 64; j++) r += netc_s[j] * Wc2[j * 3 + t];
        out[OFF_C + v * 3 + t] = r;
    } else if (t == 3) {
        float r = bd1[0];
        #pragma unroll 8
        for (int c = 0; c < 256; c++) r += f_s[c] * Wd1[c];
        out[OFF_D + v] = fmaxf(r, 0.f);
    }
}

// =====================================================================
extern "C" void kernel_launch(void* const* d_in, const int* in_sizes, int n_in,
                              void* d_out, int out_size)
{
    const float* poses = (const float*)d_in[0];
    const float* t_ped = (const float*)d_in[1];
    const float* w     = (const float*)d_in[2];
    const float* wpts  = (const float*)d_in[3];
    const float* nodes = (const float*)d_in[4];
    const float* lc    = (const float*)d_in[5];
    const float *Wec1 = (const float*)d_in[6],  *bec1 = (const float*)d_in[7];
    const float *Wec21= (const float*)d_in[8],  *bec21= (const float*)d_in[9];
    const float *Wec22= (const float*)d_in[10], *bec22= (const float*)d_in[11];
    const float *Wdc1 = (const float*)d_in[12], *bdc1 = (const float*)d_in[13];
    const float *Wdc21= (const float*)d_in[14], *bdc21= (const float*)d_in[15];
    const float *Wdc22= (const float*)d_in[16], *bdc22= (const float*)d_in[17];
    const float *Wf1  = (const float*)d_in[18], *bf1  = (const float*)d_in[19];
    const float *Wf2  = (const float*)d_in[20], *bf2  = (const float*)d_in[21];
    const float *Wf3  = (const float*)d_in[22], *bf3  = (const float*)d_in[23];
    const float *Wf4  = (const float*)d_in[24], *bf4  = (const float*)d_in[25];
    const float *Wc1  = (const float*)d_in[26], *bc1  = (const float*)d_in[27];
    const float *Wc2  = (const float*)d_in[28], *bc2  = (const float*)d_in[29];
    const float *Wd1  = (const float*)d_in[30], *bd1  = (const float*)d_in[31];
    float* out = (float*)d_out;

    setup_kernel<<<N_NODES, 128>>>(poses, t_ped, w,
                                   Wec1, bec1, Wec21, bec21, Wec22, bec22,
                                   Wdc1, bdc1, Wdc21, bdc21, Wdc22, bdc22,
                                   Wf1, bf1, out);
    bweight_kernel<<<V_PTS / 256, 256>>>(wpts, nodes);
    transpose_kernel<<<N_NODES, 256>>>(Wf1, Wf2, Wf3, Wf4);

    cudaFuncSetAttribute(field_kernel,
                         cudaFuncAttributeMaxDynamicSharedMemorySize,
                         SM_TOT * (int)sizeof(float));
    field_kernel<<<dim3(V_PTS / 128, NG), 512, SM_TOT * sizeof(float)>>>(
        lc, bf2, bf3, bf4);

    head_kernel<<<V_PTS, 64>>>(Wc1, bc1, Wc2, bc2, Wd1, bd1, out);
}

// round 9
// speedup vs baseline: 3.0347x; 3.0347x over previous
#include <cuda_runtime.h>
#include <cstdint>

#define N_NODES 128
#define V_PTS   2048
#define XYZ     63
#define NG      9          // node groups: 8 groups of 15 + 1 group of 8

// ---- output layout ----
#define OFF_C      0
#define OFF_D      6144
#define OFF_EI     8192
#define OFF_DELTA  12288
#define OFF_MEAN   12672
#define OFF_LOGVAR 13696

// ---- scratch ----
__device__ float g_ei[N_NODES * 32];
__device__ float g_b1eff[N_NODES * 64];
__device__ float g_e[N_NODES * V_PTS];
__device__ float g_fpart[NG * V_PTS * 256];
// per-node packed weight image: tf32-rounded, stride-68 padded rows
// W1 [64x68]=4352 | W2 4352 | W3 4352 | W4 [256x68]=17408  => 30464 floats = 7616 float4
__device__ float4 g_Wpad4[N_NODES * 7616];

// ---- field smem layout (float offsets) ----
#define F_BUFA 0        // 128 x 68 activation buffer
#define F_BUFB 8704
#define F_W1   17408    // 64 x 68
#define F_W2   21760
#define F_W3   26112
#define F_W4   30464    // 256 x 68
#define F_B1   47872
#define F_B2   47936
#define F_B3   48000
#define F_B4   48064
#define F_E    48320
#define F_TOT  48448    // 193792 bytes

__device__ __forceinline__ float to_tf32(float x) {
    uint32_t r;
    asm("cvt.rna.tf32.f32 %0, %1;" : "=r"(r) : "f"(x));
    return __uint_as_float(r);
}

__device__ __forceinline__ void mma_tf32(float c[4], uint32_t a0, uint32_t a1,
                                         uint32_t a2, uint32_t a3,
                                         uint32_t b0, uint32_t b1) {
    asm volatile(
        "mma.sync.aligned.m16n8k8.row.col.f32.tf32.tf32.f32 "
        "{%0,%1,%2,%3}, {%4,%5,%6,%7}, {%8,%9}, {%0,%1,%2,%3};"
        : "+f"(c[0]), "+f"(c[1]), "+f"(c[2]), "+f"(c[3])
        : "r"(a0), "r"(a1), "r"(a2), "r"(a3), "r"(b0), "r"(b1));
}

// one warp computes a 16x32 tile of C[128 x N] = A[128 x 64] * W[N x 64]^T
// c[n8][4] accumulators; rows mb*16 + (lane>>2) and +8; cols cb + n8*8 + (lane&3)*2 +{0,1}
__device__ __forceinline__ void gemm16x32(const float* __restrict__ Ain,
                                          const float* __restrict__ Ws,
                                          int mb, int cb, int lane,
                                          float c[4][4]) {
    int r  = mb * 16 + (lane >> 2);
    int kk = lane & 3;
    const float* ar0 = Ain + r * 68 + kk;
    const float* ar1 = Ain + (r + 8) * 68 + kk;
    const float* bc  = Ws + (cb + (lane >> 2)) * 68 + kk;
    #pragma unroll
    for (int k8 = 0; k8 < 8; k8++) {
        uint32_t a0 = __float_as_uint(ar0[k8 * 8]);
        uint32_t a1 = __float_as_uint(ar1[k8 * 8]);
        uint32_t a2 = __float_as_uint(ar0[k8 * 8 + 4]);
        uint32_t a3 = __float_as_uint(ar1[k8 * 8 + 4]);
        #pragma unroll
        for (int n8 = 0; n8 < 4; n8++) {
            uint32_t b0 = __float_as_uint(bc[n8 * 8 * 68 + k8 * 8]);
            uint32_t b1 = __float_as_uint(bc[n8 * 8 * 68 + k8 * 8 + 4]);
            mma_tf32(c[n8], a0, a1, a2, a3, b0, b1);
        }
    }
}

// =====================================================================
// Kernel A: encoder + decoder + effective L1 bias (fp32 exact)
// =====================================================================
__global__ void setup_kernel(
    const float* __restrict__ poses, const float* __restrict__ t_ped,
    const float* __restrict__ w,
    const float* __restrict__ Wec1, const float* __restrict__ bec1,
    const float* __restrict__ Wec21, const float* __restrict__ bec21,
    const float* __restrict__ Wec22, const float* __restrict__ bec22,
    const float* __restrict__ Wdc1, const float* __restrict__ bdc1,
    const float* __restrict__ Wdc21, const float* __restrict__ bdc21,
    const float* __restrict__ Wdc22, const float* __restrict__ bdc22,
    const float* __restrict__ Wf1, const float* __restrict__ bf1,
    float* __restrict__ out)
{
    int n = blockIdx.x;
    int t = threadIdx.x;
    __shared__ float s_in[88], s_net[64], s_mean[8], s_din[80], s_net2[64], s_ei[32];

    if (t < 72)       s_in[t] = w[n * 24 + t / 3] * poses[n * 72 + t];
    else if (t < 88)  s_in[t] = t_ped[t - 72];
    __syncthreads();

    if (t < 64) {
        float a = bec1[n * 64 + t];
        const float* Wr = &Wec1[(n * 64 + t) * 88];
        #pragma unroll 8
        for (int c = 0; c < 88; c++) a += Wr[c] * s_in[c];
        s_net[t] = fmaxf(a, 0.f);
    }
    __syncthreads();

    if (t < 8) {
        float m = bec21[n * 8 + t], lv = bec22[n * 8 + t];
        const float* Wm = &Wec21[(n * 8 + t) * 64];
        const float* Wl = &Wec22[(n * 8 + t) * 64];
        #pragma unroll 8
        for (int c = 0; c < 64; c++) { m += Wm[c] * s_net[c]; lv += Wl[c] * s_net[c]; }
        s_mean[t] = m;
        out[OFF_MEAN + n * 8 + t] = m;
        out[OFF_LOGVAR + n * 8 + t] = lv;
    }
    __syncthreads();

    if (t < 72)      s_din[t] = s_in[t];
    else if (t < 80) s_din[t] = s_mean[t - 72];
    __syncthreads();

    if (t < 64) {
        float a = bdc1[n * 64 + t];
        const float* Wr = &Wdc1[(n * 64 + t) * 80];
        #pragma unroll 8
        for (int c = 0; c < 80; c++) a += Wr[c] * s_din[c];
        s_net2[t] = fmaxf(a, 0.f);
    }
    __syncthreads();

    if (t < 32) {
        float a = bdc21[n * 32 + t];
        const float* Wr = &Wdc21[(n * 32 + t) * 64];
        #pragma unroll 8
        for (int c = 0; c < 64; c++) a += Wr[c] * s_net2[c];
        s_ei[t] = a;
        g_ei[n * 32 + t] = a;
        out[OFF_EI + n * 32 + t] = a;
    }
    if (t >= 32 && t < 35) {
        int j = t - 32;
        float a = bdc22[n * 3 + j];
        const float* Wr = &Wdc22[(n * 3 + j) * 64];
        #pragma unroll 8
        for (int c = 0; c < 64; c++) a += Wr[c] * s_net2[c];
        out[OFF_DELTA + n * 3 + j] = a;
    }
    __syncthreads();

    if (t < 64) {
        float a = bf1[n * 64 + t];
        const float* Wr = &Wf1[(size_t)(n * 64 + t) * 95];
        #pragma unroll 8
        for (int c = 0; c < 32; c++) a += Wr[c] * s_ei[c];
        g_b1eff[n * 64 + t] = a;
    }
}

// =====================================================================
// Kernel B: RBF blend weights, normalized (fp32 exact)
// =====================================================================
__global__ void bweight_kernel(const float* __restrict__ wpts,
                               const float* __restrict__ nodes_posed)
{
    int v = blockIdx.x * blockDim.x + threadIdx.x;
    if (v >= V_PTS) return;
    float px = wpts[v * 3 + 0], py = wpts[v * 3 + 1], pz = wpts[v * 3 + 2];
    float denom = 0.f;
    for (int n = 0; n < N_NODES; n++) {
        float dx = px - nodes_posed[n * 3 + 0];
        float dy = py - nodes_posed[n * 3 + 1];
        float dz = pz - nodes_posed[n * 3 + 2];
        float d2 = dx * dx + dy * dy + dz * dz;
        float influ = expf(-d2 * (1.0f / 0.18f)) - 0.01f;
        float e = (influ >= 0.f) ? (influ + 1e-7f) : 0.f;
        denom += fmaxf(influ, 0.f) + 1e-7f;
        g_e[n * V_PTS + v] = e;
    }
    float inv = 1.0f / denom;
    for (int n = 0; n < N_NODES; n++) g_e[n * V_PTS + v] *= inv;
}

// =====================================================================
// Kernel E: prepack weights -> tf32, stride-68 padded rows
// =====================================================================
__global__ void prepack_kernel(const float* __restrict__ Wf1,
                               const float* __restrict__ Wf2,
                               const float* __restrict__ Wf3,
                               const float* __restrict__ Wf4)
{
    int n = blockIdx.x, tid = threadIdx.x;   // 256 threads
    float* dst = (float*)&g_Wpad4[(size_t)n * 7616];

    for (int i = tid; i < 4352; i += 256) {            // W1 [64 x 68]
        int j = i / 68, k = i - j * 68;
        float v = (k < XYZ) ? Wf1[(size_t)(n * 64 + j) * 95 + 32 + k] : 0.f;
        dst[i] = to_tf32(v);
    }
    for (int i = tid; i < 4352; i += 256) {            // W2
        int j = i / 68, k = i - j * 68;
        float v = (k < 64) ? Wf2[(size_t)n * 4096 + j * 64 + k] : 0.f;
        dst[4352 + i] = to_tf32(v);
    }
    for (int i = tid; i < 4352; i += 256) {            // W3
        int j = i / 68, k = i - j * 68;
        float v = (k < 64) ? Wf3[(size_t)n * 4096 + j * 64 + k] : 0.f;
        dst[8704 + i] = to_tf32(v);
    }
    for (int i = tid; i < 17408; i += 256) {           // W4 [256 x 68]
        int j = i / 68, k = i - j * 68;
        float v = (k < 64) ? Wf4[(size_t)n * 16384 + j * 64 + k] : 0.f;
        dst[13056 + i] = to_tf32(v);
    }
}

// =====================================================================
// Kernel C: feature field via mma.sync tf32 (HMMA)
// grid = (16 v-tiles) x (9 node-groups), 512 threads (16 warps)
// =====================================================================
__global__ void __launch_bounds__(512, 1) field_kernel(
    const float* __restrict__ local_coords,
    const float* __restrict__ bf2, const float* __restrict__ bf3,
    const float* __restrict__ bf4)
{
    extern __shared__ float sm[];
    int tid  = threadIdx.x;
    int wid  = tid >> 5, lane = tid & 31;
    int mb   = wid & 7;            // M-block (16 rows)
    int nhi  = wid >> 3;           // 0/1: which 32-col block within 64
    int v0 = blockIdx.x * 128;
    int g  = blockIdx.y;
    int n0 = g * 15;
    int ncnt = (g == 8) ? 8 : 15;

    // blend accumulator: rows (mb*16 + lane>>2) and +8; cols per round
    float acc[64];
    #pragma unroll
    for (int i = 0; i < 64; i++) acc[i] = 0.f;

    int r0 = mb * 16 + (lane >> 2);

    for (int ni = 0; ni < ncnt; ni++) {
        int n = n0 + ni;
        __syncthreads();   // previous node's reads done before overwrite

        // ---- stage weights (raw float4 copy of prepacked image) ----
        {
            const float4* src = &g_Wpad4[(size_t)n * 7616];
            float4* dst = ((float4*)sm) + (F_W1 / 4);
            #pragma unroll 4
            for (int i = tid; i < 7616; i += 512) dst[i] = src[i];
        }
        if (tid < 64) {
            sm[F_B1 + tid] = g_b1eff[n * 64 + tid];
            sm[F_B2 + tid] = bf2[n * 64 + tid];
            sm[F_B3 + tid] = bf3[n * 64 + tid];
        }
        if (tid < 256) sm[F_B4 + tid] = bf4[n * 256 + tid];
        if (tid < 128) sm[F_E + tid]  = g_e[(size_t)n * V_PTS + v0 + tid];
        // ---- stage A0 = lc tile [128 x 64] tf32 (col 63 zero) ----
        for (int i = tid; i < 8192; i += 512) {
            int v = i >> 6, k = i & 63;
            float val = (k < XYZ)
                ? local_coords[((size_t)n * V_PTS + v0 + v) * XYZ + k] : 0.f;
            sm[F_BUFA + v * 68 + k] = to_tf32(val);
        }
        __syncthreads();

        float ev0 = sm[F_E + r0];
        float ev1 = sm[F_E + r0 + 8];

        // ================= L1: bufA -> bufB =================
        {
            float c[4][4];
            #pragma unroll
            for (int a = 0; a < 4; a++)
                #pragma unroll
                for (int b = 0; b < 4; b++) c[a][b] = 0.f;
            int cb = nhi * 32;
            gemm16x32(sm + F_BUFA, sm + F_W1, mb, cb, lane, c);
            #pragma unroll
            for (int n8 = 0; n8 < 4; n8++) {
                int cc = cb + n8 * 8 + (lane & 3) * 2;
                float b0 = sm[F_B1 + cc], b1 = sm[F_B1 + cc + 1];
                sm[F_BUFB + r0 * 68 + cc]           = to_tf32(fmaxf(c[n8][0] + b0, 0.f));
                sm[F_BUFB + r0 * 68 + cc + 1]       = to_tf32(fmaxf(c[n8][1] + b1, 0.f));
                sm[F_BUFB + (r0 + 8) * 68 + cc]     = to_tf32(fmaxf(c[n8][2] + b0, 0.f));
                sm[F_BUFB + (r0 + 8) * 68 + cc + 1] = to_tf32(fmaxf(c[n8][3] + b1, 0.f));
            }
        }
        __syncthreads();

        // ================= L2: bufB -> bufA =================
        {
            float c[4][4];
            #pragma unroll
            for (int a = 0; a < 4; a++)
                #pragma unroll
                for (int b = 0; b < 4; b++) c[a][b] = 0.f;
            int cb = nhi * 32;
            gemm16x32(sm + F_BUFB, sm + F_W2, mb, cb, lane, c);
            #pragma unroll
            for (int n8 = 0; n8 < 4; n8++) {
                int cc = cb + n8 * 8 + (lane & 3) * 2;
                float b0 = sm[F_B2 + cc], b1 = sm[F_B2 + cc + 1];
                sm[F_BUFA + r0 * 68 + cc]           = to_tf32(fmaxf(c[n8][0] + b0, 0.f));
                sm[F_BUFA + r0 * 68 + cc + 1]       = to_tf32(fmaxf(c[n8][1] + b1, 0.f));
                sm[F_BUFA + (r0 + 8) * 68 + cc]     = to_tf32(fmaxf(c[n8][2] + b0, 0.f));
                sm[F_BUFA + (r0 + 8) * 68 + cc + 1] = to_tf32(fmaxf(c[n8][3] + b1, 0.f));
            }
        }
        __syncthreads();

        // ================= L3: bufA -> bufB =================
        {
            float c[4][4];
            #pragma unroll
            for (int a = 0; a < 4; a++)
                #pragma unroll
                for (int b = 0; b < 4; b++) c[a][b] = 0.f;
            int cb = nhi * 32;
            gemm16x32(sm + F_BUFA, sm + F_W3, mb, cb, lane, c);
            #pragma unroll
            for (int n8 = 0; n8 < 4; n8++) {
                int cc = cb + n8 * 8 + (lane & 3) * 2;
                float b0 = sm[F_B3 + cc], b1 = sm[F_B3 + cc + 1];
                sm[F_BUFB + r0 * 68 + cc]           = to_tf32(fmaxf(c[n8][0] + b0, 0.f));
                sm[F_BUFB + r0 * 68 + cc + 1]       = to_tf32(fmaxf(c[n8][1] + b1, 0.f));
                sm[F_BUFB + (r0 + 8) * 68 + cc]     = to_tf32(fmaxf(c[n8][2] + b0, 0.f));
                sm[F_BUFB + (r0 + 8) * 68 + cc + 1] = to_tf32(fmaxf(c[n8][3] + b1, 0.f));
            }
        }
        __syncthreads();

        // ================= L4: bufB x W4 (256 cols, 4 rounds) =================
        #pragma unroll
        for (int rnd = 0; rnd < 4; rnd++) {
            float c[4][4];
            #pragma unroll
            for (int a = 0; a < 4; a++)
                #pragma unroll
                for (int b = 0; b < 4; b++) c[a][b] = 0.f;
            int cb = rnd * 64 + nhi * 32;
            gemm16x32(sm + F_BUFB, sm + F_W4, mb, cb, lane, c);
            #pragma unroll
            for (int n8 = 0; n8 < 4; n8++) {
                int cc = cb + n8 * 8 + (lane & 3) * 2;
                float b0 = sm[F_B4 + cc], b1 = sm[F_B4 + cc + 1];
                int ai = rnd * 16 + n8 * 4;
                acc[ai + 0] += ev0 * fmaxf(c[n8][0] + b0, 0.f);
                acc[ai + 1] += ev0 * fmaxf(c[n8][1] + b1, 0.f);
                acc[ai + 2] += ev1 * fmaxf(c[n8][2] + b0, 0.f);
                acc[ai + 3] += ev1 * fmaxf(c[n8][3] + b1, 0.f);
            }
        }
    }

    // ---- write this group's partial tile ----
    {
        size_t base0 = ((size_t)g * V_PTS + v0 + r0) * 256;
        size_t base1 = ((size_t)g * V_PTS + v0 + r0 + 8) * 256;
        #pragma unroll
        for (int rnd = 0; rnd < 4; rnd++) {
            #pragma unroll
            for (int n8 = 0; n8 < 4; n8++) {
                int cc = rnd * 64 + nhi * 32 + n8 * 8 + (lane & 3) * 2;
                int ai = rnd * 16 + n8 * 4;
                *(float2*)&g_fpart[base0 + cc] = make_float2(acc[ai + 0], acc[ai + 1]);
                *(float2*)&g_fpart[base1 + cc] = make_float2(acc[ai + 2], acc[ai + 3]);
            }
        }
    }
}

// =====================================================================
// Kernel D: reduce partials + NeRF head
// =====================================================================
__global__ void head_kernel(const float* __restrict__ Wc1, const float* __restrict__ bc1,
                            const float* __restrict__ Wc2, const float* __restrict__ bc2,
                            const float* __restrict__ Wd1, const float* __restrict__ bd1,
                            float* __restrict__ out)
{
    int v = blockIdx.x;
    int t = threadIdx.x;   // 64 threads
    __shared__ float f_s[256];
    __shared__ float netc_s[64];

    {
        float4 s = make_float4(0.f, 0.f, 0.f, 0.f);
        #pragma unroll
        for (int g2 = 0; g2 < NG; g2++) {
            float4 p = *(const float4*)&g_fpart[((size_t)g2 * V_PTS + v) * 256 + t * 4];
            s.x += p.x; s.y += p.y; s.z += p.z; s.w += p.w;
        }
        *(float4*)&f_s[t * 4] = s;
    }
    __syncthreads();

    float a = bc1[t];
    #pragma unroll 8
    for (int c = 0; c < 256; c++) a += f_s[c] * Wc1[c * 64 + t];
    netc_s[t] = fmaxf(a, 0.f);
    __syncthreads();

    if (t < 3) {
        float r = bc2[t];
        #pragma unroll 8
        for (int j = 0; j < 64; j++) r += netc_s[j] * Wc2[j * 3 + t];
        out[OFF_C + v * 3 + t] = r;
    } else if (t == 3) {
        float r = bd1[0];
        #pragma unroll 8
        for (int c = 0; c < 256; c++) r += f_s[c] * Wd1[c];
        out[OFF_D + v] = fmaxf(r, 0.f);
    }
}

// =====================================================================
extern "C" void kernel_launch(void* const* d_in, const int* in_sizes, int n_in,
                              void* d_out, int out_size)
{
    const float* poses = (const float*)d_in[0];
    const float* t_ped = (const float*)d_in[1];
    const float* w     = (const float*)d_in[2];
    const float* wpts  = (const float*)d_in[3];
    const float* nodes = (const float*)d_in[4];
    const float* lc    = (const float*)d_in[5];
    const float *Wec1 = (const float*)d_in[6],  *bec1 = (const float*)d_in[7];
    const float *Wec21= (const float*)d_in[8],  *bec21= (const float*)d_in[9];
    const float *Wec22= (const float*)d_in[10], *bec22= (const float*)d_in[11];
    const float *Wdc1 = (const float*)d_in[12], *bdc1 = (const float*)d_in[13];
    const float *Wdc21= (const float*)d_in[14], *bdc21= (const float*)d_in[15];
    const float *Wdc22= (const float*)d_in[16], *bdc22= (const float*)d_in[17];
    const float *Wf1  = (const float*)d_in[18], *bf1  = (const float*)d_in[19];
    const float *Wf2  = (const float*)d_in[20], *bf2  = (const float*)d_in[21];
    const float *Wf3  = (const float*)d_in[22], *bf3  = (const float*)d_in[23];
    const float *Wf4  = (const float*)d_in[24], *bf4  = (const float*)d_in[25];
    const float *Wc1  = (const float*)d_in[26], *bc1  = (const float*)d_in[27];
    const float *Wc2  = (const float*)d_in[28], *bc2  = (const float*)d_in[29];
    const float *Wd1  = (const float*)d_in[30], *bd1  = (const float*)d_in[31];
    float* out = (float*)d_out;

    setup_kernel<<<N_NODES, 128>>>(poses, t_ped, w,
                                   Wec1, bec1, Wec21, bec21, Wec22, bec22,
                                   Wdc1, bdc1, Wdc21, bdc21, Wdc22, bdc22,
                                   Wf1, bf1, out);
    bweight_kernel<<<V_PTS / 256, 256>>>(wpts, nodes);
    prepack_kernel<<<N_NODES, 256>>>(Wf1, Wf2, Wf3, Wf4);

    cudaFuncSetAttribute(field_kernel,
                         cudaFuncAttributeMaxDynamicSharedMemorySize,
                         F_TOT * (int)sizeof(float));
    field_kernel<<<dim3(V_PTS / 128, NG), 512, F_TOT * sizeof(float)>>>(lc, bf2, bf3, bf4);

    head_kernel<<<V_PTS, 64>>>(Wc1, bc1, Wc2, bc2, Wd1, bd1, out);
}